// round 5
// baseline (speedup 1.0000x reference)
#include <cuda_runtime.h>
#include <math.h>
#include <stdint.h>

#define N_EMBED 1024
#define SLEN    2048
#define BATCH   4
#define NHEADS  16
#define HDIM    64
#define MROWS   (BATCH * SLEN)        // 8192

// Scratch (device globals: allocation-free rule)
__device__ float g_qkv[(size_t)MROWS * 3 * N_EMBED];  // [8192, 3072]
__device__ float g_y[(size_t)MROWS * N_EMBED];        // [8192, 1024]

// ---------------------------------------------------------------------------
// Helpers
// ---------------------------------------------------------------------------
__device__ __forceinline__ uint32_t f2tf32(float f) {
    uint32_t r;
    asm("cvt.rna.tf32.f32 %0, %1;" : "=r"(r) : "f"(f));
    return r;
}
__device__ __forceinline__ void mma_tf32(float d[4], const uint32_t a[4], const uint32_t b[2]) {
    asm volatile(
        "mma.sync.aligned.m16n8k8.row.col.f32.tf32.tf32.f32 "
        "{%0,%1,%2,%3}, {%4,%5,%6,%7}, {%8,%9}, {%0,%1,%2,%3};"
        : "+f"(d[0]), "+f"(d[1]), "+f"(d[2]), "+f"(d[3])
        : "r"(a[0]), "r"(a[1]), "r"(a[2]), "r"(a[3]), "r"(b[0]), "r"(b[1]));
}
__device__ __forceinline__ uint32_t smem_u32(const void* p) {
    uint32_t a;
    asm("{ .reg .u64 t; cvta.to.shared.u64 t, %1; cvt.u32.u64 %0, t; }" : "=r"(a) : "l"(p));
    return a;
}
__device__ __forceinline__ void cp_async16(uint32_t saddr, const void* g) {
    asm volatile("cp.async.cg.shared.global [%0], [%1], 16;" :: "r"(saddr), "l"(g));
}
#define CP_COMMIT()  asm volatile("cp.async.commit_group;" ::: "memory")
#define CP_WAIT(n)   asm volatile("cp.async.wait_group %0;" :: "n"(n) : "memory")

// ---------------------------------------------------------------------------
// tf32 mma.sync GEMM v2: C[M,N] = A[M,K] @ B[K,N] + bias[N]
// BM=BN=128, BK=16, 256 threads (8 warps, 2x4), warp tile 64x32.
// 3-stage cp.async pipeline (raw fp32 smem), tf32 cvt on fragment registers.
// Dynamic smem: 3 * (128*20 + 16*136) floats = 56832 bytes.
// ---------------------------------------------------------------------------
#define G_AS 20
#define G_BS 136
#define G_ASTG (128 * G_AS)
#define G_BSTG (16 * G_BS)
#define G_SMEM_WORDS (3 * (G_ASTG + G_BSTG))

__global__ __launch_bounds__(256)
void mma_gemm_kernel(const float* __restrict__ A, const float* __restrict__ B,
                     const float* __restrict__ bias, float* __restrict__ C,
                     int M, int N, int K) {
    extern __shared__ float gsm[];
    float* Asm = gsm;                       // [3][128*20]
    float* Bsm = gsm + 3 * G_ASTG;          // [3][16*136]

    const int tid   = threadIdx.x;
    const int lane  = tid & 31;
    const int wid   = tid >> 5;
    const int gid   = lane >> 2;
    const int tig   = lane & 3;
    const int warpM = wid >> 2;
    const int warpN = wid & 3;
    const int row0  = blockIdx.y * 128;
    const int col0  = blockIdx.x * 128;

    const uint32_t uA = smem_u32(Asm);
    const uint32_t uB = smem_u32(Bsm);

    // Per-thread load mapping (2 x 16B chunks each for A and B per stage)
    const int arow0 = tid >> 2,        ac0 = (tid & 3) * 4;
    const int arow1 = (tid + 256) >> 2, ac1 = ((tid + 256) & 3) * 4;
    const int brow0 = tid >> 5,        bc0 = (tid & 31) * 4;
    const int brow1 = (tid + 256) >> 5, bc1 = ((tid + 256) & 31) * 4;

    auto issue = [&](int kt, int stg) {
        const float* Ag = A + (size_t)row0 * K + kt * 16;
        const float* Bg = B + (size_t)(kt * 16) * N + col0;
        const uint32_t sa = uA + (uint32_t)(stg * G_ASTG) * 4;
        const uint32_t sb = uB + (uint32_t)(stg * G_BSTG) * 4;
        cp_async16(sa + (uint32_t)(arow0 * G_AS + ac0) * 4, Ag + (size_t)arow0 * K + ac0);
        cp_async16(sa + (uint32_t)(arow1 * G_AS + ac1) * 4, Ag + (size_t)arow1 * K + ac1);
        cp_async16(sb + (uint32_t)(brow0 * G_BS + bc0) * 4, Bg + (size_t)brow0 * N + bc0);
        cp_async16(sb + (uint32_t)(brow1 * G_BS + bc1) * 4, Bg + (size_t)brow1 * N + bc1);
        CP_COMMIT();
    };

    float acc[4][4][4];
    #pragma unroll
    for (int i = 0; i < 4; i++)
        #pragma unroll
        for (int j = 0; j < 4; j++)
            #pragma unroll
            for (int r = 0; r < 4; r++) acc[i][j][r] = 0.f;

    const int NT = K / 16;

    issue(0, 0);
    issue(1, 1);

    for (int kt = 0; kt < NT; kt++) {
        if (kt + 2 < NT) { CP_WAIT(1); } else { CP_WAIT(0); }
        __syncthreads();
        if (kt + 2 < NT) issue(kt + 2, (kt + 2) % 3);

        const int stg = kt % 3;
        const float* As = Asm + stg * G_ASTG;
        const float* Bs = Bsm + stg * G_BSTG;

        #pragma unroll
        for (int ks = 0; ks < 2; ks++) {
            const int kb = ks * 8;
            uint32_t a[4][4], b[4][2];
            #pragma unroll
            for (int mf = 0; mf < 4; mf++) {
                const int r = warpM * 64 + mf * 16;
                a[mf][0] = f2tf32(As[(r + gid)     * G_AS + kb + tig]);
                a[mf][1] = f2tf32(As[(r + gid + 8) * G_AS + kb + tig]);
                a[mf][2] = f2tf32(As[(r + gid)     * G_AS + kb + tig + 4]);
                a[mf][3] = f2tf32(As[(r + gid + 8) * G_AS + kb + tig + 4]);
            }
            #pragma unroll
            for (int nf = 0; nf < 4; nf++) {
                const int c = warpN * 32 + nf * 8 + gid;
                b[nf][0] = f2tf32(Bs[(kb + tig)     * G_BS + c]);
                b[nf][1] = f2tf32(Bs[(kb + tig + 4) * G_BS + c]);
            }
            #pragma unroll
            for (int mf = 0; mf < 4; mf++)
                #pragma unroll
                for (int nf = 0; nf < 4; nf++)
                    mma_tf32(acc[mf][nf], a[mf], b[nf]);
        }
    }

    // Epilogue: add bias, store fp32
    #pragma unroll
    for (int mf = 0; mf < 4; mf++) {
        const size_t rbase = (size_t)row0 + warpM * 64 + mf * 16 + gid;
        #pragma unroll
        for (int nf = 0; nf < 4; nf++) {
            const int col = col0 + warpN * 32 + nf * 8 + tig * 2;
            const float2 bz = *reinterpret_cast<const float2*>(bias + col);
            float2 v0, v1;
            v0.x = acc[mf][nf][0] + bz.x; v0.y = acc[mf][nf][1] + bz.y;
            v1.x = acc[mf][nf][2] + bz.x; v1.y = acc[mf][nf][3] + bz.y;
            *reinterpret_cast<float2*>(C + rbase * N + col)       = v0;
            *reinterpret_cast<float2*>(C + (rbase + 8) * N + col) = v1;
        }
    }
}

// ---------------------------------------------------------------------------
// Flash attention (tf32 mma.sync) — unchanged from R4 (passed, 5.8e-4).
// ---------------------------------------------------------------------------
#define STR 76

__global__ __launch_bounds__(256)
void flash_attn_mma_kernel(const float* __restrict__ qkv, float* __restrict__ y) {
    extern __shared__ uint32_t sm[];
    uint32_t* Khi = sm;
    uint32_t* Klo = sm + 64 * STR;
    uint32_t* Vs  = sm + 128 * STR;
    uint32_t* Ps  = sm + 192 * STR;
    uint32_t* Qhi = sm;
    uint32_t* Qlo = sm + 128 * STR;

    const int qt  = blockIdx.x;
    const int h   = blockIdx.y;
    const int b   = blockIdx.z;
    const int tid = threadIdx.x;
    const int lane = tid & 31;
    const int wid  = tid >> 5;
    const int gid  = lane >> 2;
    const int tig  = lane & 3;
    const int q0   = qt * 128;
    const int wrow = wid * 16;
    const size_t rowbase = (size_t)b * SLEN;

    #pragma unroll
    for (int it = 0; it < 8; it++) {
        const int idx = it * 256 + tid;
        const int r = idx >> 4, c4 = idx & 15;
        const float* qp = qkv + (rowbase + q0 + r) * 3072 + h * 64 + c4 * 4;
        const float4 v = *reinterpret_cast<const float4*>(qp);
        const float f[4] = {v.x * 0.125f, v.y * 0.125f, v.z * 0.125f, v.w * 0.125f};
        #pragma unroll
        for (int j = 0; j < 4; j++) {
            const uint32_t hi = f2tf32(f[j]);
            Qhi[r * STR + c4 * 4 + j] = hi;
            Qlo[r * STR + c4 * 4 + j] = f2tf32(f[j] - __uint_as_float(hi));
        }
    }
    __syncthreads();

    uint32_t qh[8][4], ql[8][4];
    #pragma unroll
    for (int kk = 0; kk < 8; kk++) {
        const int ba = (wrow + gid) * STR + kk * 8;
        const int bb = (wrow + gid + 8) * STR + kk * 8;
        qh[kk][0] = Qhi[ba + tig];     qh[kk][1] = Qhi[bb + tig];
        qh[kk][2] = Qhi[ba + tig + 4]; qh[kk][3] = Qhi[bb + tig + 4];
        ql[kk][0] = Qlo[ba + tig];     ql[kk][1] = Qlo[bb + tig];
        ql[kk][2] = Qlo[ba + tig + 4]; ql[kk][3] = Qlo[bb + tig + 4];
    }

    float oacc[8][4];
    #pragma unroll
    for (int nf = 0; nf < 8; nf++)
        #pragma unroll
        for (int e = 0; e < 4; e++) oacc[nf][e] = 0.f;
    float m0 = -INFINITY, m1 = -INFINITY, l0 = 0.f, l1 = 0.f;

    const int row0g = q0 + wrow + gid;
    const int row1g = row0g + 8;
    const int kend  = q0 + 128;

    for (int kb = 0; kb < kend; kb += 64) {
        __syncthreads();

        #pragma unroll
        for (int it = 0; it < 4; it++) {
            const int idx = it * 256 + tid;
            const int r = idx >> 4, c4 = idx & 15;
            const float* kp = qkv + (rowbase + kb + r) * 3072 + N_EMBED + h * 64 + c4 * 4;
            const float4 kv = *reinterpret_cast<const float4*>(kp);
            const float4 vv = *reinterpret_cast<const float4*>(kp + N_EMBED);
            const float kf[4] = {kv.x, kv.y, kv.z, kv.w};
            const float vf[4] = {vv.x, vv.y, vv.z, vv.w};
            #pragma unroll
            for (int j = 0; j < 4; j++) {
                const uint32_t hi = f2tf32(kf[j]);
                Khi[r * STR + c4 * 4 + j] = hi;
                Klo[r * STR + c4 * 4 + j] = f2tf32(kf[j] - __uint_as_float(hi));
                Vs [r * STR + c4 * 4 + j] = f2tf32(vf[j]);
            }
        }
        __syncthreads();

        float sacc[8][4];
        #pragma unroll
        for (int nf = 0; nf < 8; nf++)
            #pragma unroll
            for (int e = 0; e < 4; e++) sacc[nf][e] = 0.f;

        #pragma unroll
        for (int kk = 0; kk < 8; kk++) {
            #pragma unroll
            for (int nf = 0; nf < 8; nf++) {
                const int kr = (nf * 8 + gid) * STR + kk * 8;
                uint32_t bh[2], bl[2];
                bh[0] = Khi[kr + tig]; bh[1] = Khi[kr + tig + 4];
                bl[0] = Klo[kr + tig]; bl[1] = Klo[kr + tig + 4];
                mma_tf32(sacc[nf], qh[kk], bh);
                mma_tf32(sacc[nf], ql[kk], bh);
                mma_tf32(sacc[nf], qh[kk], bl);
            }
        }

        if (kb + 63 > q0 + wrow) {
            #pragma unroll
            for (int nf = 0; nf < 8; nf++) {
                const int c = kb + nf * 8 + tig * 2;
                if (c     > row0g) sacc[nf][0] = -INFINITY;
                if (c + 1 > row0g) sacc[nf][1] = -INFINITY;
                if (c     > row1g) sacc[nf][2] = -INFINITY;
                if (c + 1 > row1g) sacc[nf][3] = -INFINITY;
            }
        }

        float mx0 = -INFINITY, mx1 = -INFINITY;
        #pragma unroll
        for (int nf = 0; nf < 8; nf++) {
            mx0 = fmaxf(mx0, fmaxf(sacc[nf][0], sacc[nf][1]));
            mx1 = fmaxf(mx1, fmaxf(sacc[nf][2], sacc[nf][3]));
        }
        mx0 = fmaxf(mx0, __shfl_xor_sync(0xffffffff, mx0, 1));
        mx0 = fmaxf(mx0, __shfl_xor_sync(0xffffffff, mx0, 2));
        mx1 = fmaxf(mx1, __shfl_xor_sync(0xffffffff, mx1, 1));
        mx1 = fmaxf(mx1, __shfl_xor_sync(0xffffffff, mx1, 2));

        const float mn0 = fmaxf(m0, mx0);
        const float mn1 = fmaxf(m1, mx1);
        const float a0 = __expf(m0 - mn0);
        const float a1 = __expf(m1 - mn1);
        m0 = mn0; m1 = mn1;

        float rs0 = 0.f, rs1 = 0.f;
        #pragma unroll
        for (int nf = 0; nf < 8; nf++) {
            const float p0 = __expf(sacc[nf][0] - m0);
            const float p1 = __expf(sacc[nf][1] - m0);
            const float p2 = __expf(sacc[nf][2] - m1);
            const float p3 = __expf(sacc[nf][3] - m1);
            rs0 += p0 + p1; rs1 += p2 + p3;
            uint2 u0; u0.x = f2tf32(p0); u0.y = f2tf32(p1);
            uint2 u1; u1.x = f2tf32(p2); u1.y = f2tf32(p3);
            *reinterpret_cast<uint2*>(&Ps[(wrow + gid)     * STR + nf * 8 + 2 * tig]) = u0;
            *reinterpret_cast<uint2*>(&Ps[(wrow + gid + 8) * STR + nf * 8 + 2 * tig]) = u1;
        }
        rs0 += __shfl_xor_sync(0xffffffff, rs0, 1);
        rs0 += __shfl_xor_sync(0xffffffff, rs0, 2);
        rs1 += __shfl_xor_sync(0xffffffff, rs1, 1);
        rs1 += __shfl_xor_sync(0xffffffff, rs1, 2);
        l0 = l0 * a0 + rs0;
        l1 = l1 * a1 + rs1;

        #pragma unroll
        for (int nf = 0; nf < 8; nf++) {
            oacc[nf][0] *= a0; oacc[nf][1] *= a0;
            oacc[nf][2] *= a1; oacc[nf][3] *= a1;
        }

        __syncwarp();

        #pragma unroll
        for (int kk = 0; kk < 8; kk++) {
            uint32_t a[4];
            const int pa = (wrow + gid) * STR + kk * 8;
            const int pb = (wrow + gid + 8) * STR + kk * 8;
            a[0] = Ps[pa + tig];     a[1] = Ps[pb + tig];
            a[2] = Ps[pa + tig + 4]; a[3] = Ps[pb + tig + 4];
            #pragma unroll
            for (int nf = 0; nf < 8; nf++) {
                uint32_t bv[2];
                bv[0] = Vs[(kk * 8 + tig)     * STR + nf * 8 + gid];
                bv[1] = Vs[(kk * 8 + tig + 4) * STR + nf * 8 + gid];
                mma_tf32(oacc[nf], a, bv);
            }
        }
    }

    const float inv0 = 1.f / l0;
    const float inv1 = 1.f / l1;
    float* yp0 = y + (rowbase + row0g) * N_EMBED + h * 64;
    float* yp1 = y + (rowbase + row1g) * N_EMBED + h * 64;
    #pragma unroll
    for (int nf = 0; nf < 8; nf++) {
        float2 v0, v1;
        v0.x = oacc[nf][0] * inv0; v0.y = oacc[nf][1] * inv0;
        v1.x = oacc[nf][2] * inv1; v1.y = oacc[nf][3] * inv1;
        *reinterpret_cast<float2*>(yp0 + nf * 8 + 2 * tig) = v0;
        *reinterpret_cast<float2*>(yp1 + nf * 8 + 2 * tig) = v1;
    }
}

// ---------------------------------------------------------------------------
// kernel_launch
// ---------------------------------------------------------------------------
extern "C" void kernel_launch(void* const* d_in, const int* in_sizes, int n_in,
                              void* d_out, int out_size) {
    const float* x      = (const float*)d_in[0];
    const float* W_attn = (const float*)d_in[1];
    const float* b_attn = (const float*)d_in[2];
    const float* W_proj = (const float*)d_in[3];
    const float* b_proj = (const float*)d_in[4];
    float* out = (float*)d_out;

    float* qkv = nullptr; float* yb = nullptr;
    cudaGetSymbolAddress((void**)&qkv, g_qkv);
    cudaGetSymbolAddress((void**)&yb,  g_y);

    const int gemm_smem = G_SMEM_WORDS * 4;   // 56832 bytes
    const int fa_smem   = 320 * STR * 4;      // 97280 bytes
    cudaFuncSetAttribute(mma_gemm_kernel,
                         cudaFuncAttributeMaxDynamicSharedMemorySize, gemm_smem);
    cudaFuncSetAttribute(flash_attn_mma_kernel,
                         cudaFuncAttributeMaxDynamicSharedMemorySize, fa_smem);

    // 1) QKV GEMM (tf32 mma.sync, cp.async pipeline)
    {
        dim3 grid(3 * N_EMBED / 128, MROWS / 128);
        mma_gemm_kernel<<<grid, 256, gemm_smem>>>(x, W_attn, b_attn, qkv,
                                                  MROWS, 3 * N_EMBED, N_EMBED);
    }
    // 2) Causal flash attention (tf32 mma.sync)
    {
        dim3 grid(SLEN / 128, NHEADS, BATCH);
        flash_attn_mma_kernel<<<grid, 256, fa_smem>>>(qkv, yb);
    }
    // 3) Output projection (tf32 mma.sync, cp.async pipeline)
    {
        dim3 grid(N_EMBED / 128, MROWS / 128);
        mma_gemm_kernel<<<grid, 256, gemm_smem>>>(yb, W_proj, b_proj, out,
                                                  MROWS, N_EMBED, N_EMBED);
    }
}

// round 6
// speedup vs baseline: 1.0535x; 1.0535x over previous
#include <cuda_runtime.h>
#include <math.h>
#include <stdint.h>

#define N_EMBED 1024
#define SLEN    2048
#define BATCH   4
#define NHEADS  16
#define HDIM    64
#define MROWS   (BATCH * SLEN)        // 8192

// Scratch (device globals: allocation-free rule)
__device__ float g_qkv[(size_t)MROWS * 3 * N_EMBED];  // [8192, 3072]
__device__ float g_y[(size_t)MROWS * N_EMBED];        // [8192, 1024]

// ---------------------------------------------------------------------------
// Helpers
// ---------------------------------------------------------------------------
__device__ __forceinline__ uint32_t f2tf32(float f) {
    uint32_t r;
    asm("cvt.rna.tf32.f32 %0, %1;" : "=r"(r) : "f"(f));
    return r;
}
__device__ __forceinline__ void mma_tf32(float d[4], const uint32_t a[4], const uint32_t b[2]) {
    asm volatile(
        "mma.sync.aligned.m16n8k8.row.col.f32.tf32.tf32.f32 "
        "{%0,%1,%2,%3}, {%4,%5,%6,%7}, {%8,%9}, {%0,%1,%2,%3};"
        : "+f"(d[0]), "+f"(d[1]), "+f"(d[2]), "+f"(d[3])
        : "r"(a[0]), "r"(a[1]), "r"(a[2]), "r"(a[3]), "r"(b[0]), "r"(b[1]));
}

// ---------------------------------------------------------------------------
// tf32 mma.sync GEMM v3: C[M,N] = A[M,K] @ B[K,N] + bias[N]
// BM=256, BN=128, BK=16; 256 threads = 8 warps (4x2), warp tile 64x64.
// Reg-staged double buffer (cvt at store). Dynamic smem:
//   A: [2][256*20] words, B: [2][16*136] words -> 58368 bytes.
// ---------------------------------------------------------------------------
#define G_AS 20
#define G_BS 136
#define G_ASTG (256 * G_AS)
#define G_BSTG (16 * G_BS)
#define G_SMEM_BYTES ((2 * (G_ASTG + G_BSTG)) * 4)

__global__ __launch_bounds__(256, 1)
void mma_gemm_kernel(const float* __restrict__ A, const float* __restrict__ B,
                     const float* __restrict__ bias, float* __restrict__ C,
                     int M, int N, int K) {
    extern __shared__ uint32_t gsm[];
    uint32_t* Asm = gsm;                    // [2][256*20]
    uint32_t* Bsm = gsm + 2 * G_ASTG;       // [2][16*136]

    const int tid   = threadIdx.x;
    const int lane  = tid & 31;
    const int wid   = tid >> 5;
    const int gid   = lane >> 2;
    const int tig   = lane & 3;
    const int warpM = wid >> 1;           // 0..3 -> 64 rows
    const int warpN = wid & 1;            // 0..1 -> 64 cols
    const int row0  = blockIdx.y * 256;
    const int col0  = blockIdx.x * 128;

    float acc[4][8][4];
    #pragma unroll
    for (int i = 0; i < 4; i++)
        #pragma unroll
        for (int j = 0; j < 8; j++)
            #pragma unroll
            for (int r = 0; r < 4; r++) acc[i][j][r] = 0.f;

    float4 av[4], bv[2];
    const int NT = K / 16;

    const int arow = tid >> 2, ac = (tid & 3) * 4;   // A: 4 chunks, rows +64
    const int brow = tid >> 5, bc = (tid & 31) * 4;  // B: 2 chunks, rows +8

    auto load_tile = [&](int kt) {
        #pragma unroll
        for (int i = 0; i < 4; i++)
            av[i] = *reinterpret_cast<const float4*>(
                A + (size_t)(row0 + arow + i * 64) * K + kt * 16 + ac);
        #pragma unroll
        for (int i = 0; i < 2; i++)
            bv[i] = *reinterpret_cast<const float4*>(
                B + (size_t)(kt * 16 + brow + i * 8) * N + col0 + bc);
    };
    auto store_tile = [&](int buf) {
        uint32_t* Ab = Asm + buf * G_ASTG;
        uint32_t* Bb = Bsm + buf * G_BSTG;
        #pragma unroll
        for (int i = 0; i < 4; i++) {
            uint32_t* ap = &Ab[(arow + i * 64) * G_AS + ac];
            ap[0] = f2tf32(av[i].x); ap[1] = f2tf32(av[i].y);
            ap[2] = f2tf32(av[i].z); ap[3] = f2tf32(av[i].w);
        }
        #pragma unroll
        for (int i = 0; i < 2; i++) {
            uint32_t* bp = &Bb[(brow + i * 8) * G_BS + bc];
            bp[0] = f2tf32(bv[i].x); bp[1] = f2tf32(bv[i].y);
            bp[2] = f2tf32(bv[i].z); bp[3] = f2tf32(bv[i].w);
        }
    };
    auto compute = [&](int buf) {
        const uint32_t* As = Asm + buf * G_ASTG;
        const uint32_t* Bs = Bsm + buf * G_BSTG;
        #pragma unroll
        for (int ks = 0; ks < 2; ks++) {
            const int kb = ks * 8;
            uint32_t a[4][4], b[8][2];
            #pragma unroll
            for (int mf = 0; mf < 4; mf++) {
                const int r = warpM * 64 + mf * 16;
                a[mf][0] = As[(r + gid)     * G_AS + kb + tig];
                a[mf][1] = As[(r + gid + 8) * G_AS + kb + tig];
                a[mf][2] = As[(r + gid)     * G_AS + kb + tig + 4];
                a[mf][3] = As[(r + gid + 8) * G_AS + kb + tig + 4];
            }
            #pragma unroll
            for (int nf = 0; nf < 8; nf++) {
                const int c = warpN * 64 + nf * 8 + gid;
                b[nf][0] = Bs[(kb + tig)     * G_BS + c];
                b[nf][1] = Bs[(kb + tig + 4) * G_BS + c];
            }
            #pragma unroll
            for (int mf = 0; mf < 4; mf++)
                #pragma unroll
                for (int nf = 0; nf < 8; nf++)
                    mma_tf32(acc[mf][nf], a[mf], b[nf]);
        }
    };

    load_tile(0);
    store_tile(0);
    __syncthreads();

    for (int kt = 0; kt < NT; kt++) {
        const int cur = kt & 1;
        const bool more = (kt + 1) < NT;
        if (more) load_tile(kt + 1);
        compute(cur);
        if (more) store_tile(cur ^ 1);
        __syncthreads();
    }

    // Epilogue: add bias, store fp32
    #pragma unroll
    for (int mf = 0; mf < 4; mf++) {
        const size_t rbase = (size_t)row0 + warpM * 64 + mf * 16 + gid;
        #pragma unroll
        for (int nf = 0; nf < 8; nf++) {
            const int col = col0 + warpN * 64 + nf * 8 + tig * 2;
            const float2 bz = *reinterpret_cast<const float2*>(bias + col);
            float2 v0, v1;
            v0.x = acc[mf][nf][0] + bz.x; v0.y = acc[mf][nf][1] + bz.y;
            v1.x = acc[mf][nf][2] + bz.x; v1.y = acc[mf][nf][3] + bz.y;
            *reinterpret_cast<float2*>(C + rbase * N + col)       = v0;
            *reinterpret_cast<float2*>(C + (rbase + 8) * N + col) = v1;
        }
    }
}

// ---------------------------------------------------------------------------
// Flash attention, tf32 mma.sync, 2-term QK split (q exact, k single-tf32).
// CTA = 128 q-rows x head x batch; 8 warps x 16 q-rows; 64-key chunks.
// SMEM words (stride 76): Kh[64*76] Vs[64*76] Ps[128*76] = 256*76
// Q staging overlay: Qhi[128*76] Qlo[128*76] (same 256*76 region).
// ---------------------------------------------------------------------------
#define STR 76
#define FA_SMEM_BYTES (256 * STR * 4)

__global__ __launch_bounds__(256)
void flash_attn_mma_kernel(const float* __restrict__ qkv, float* __restrict__ y) {
    extern __shared__ uint32_t sm[];
    uint32_t* Kh  = sm;                      // 64*76
    uint32_t* Vs  = sm + 64 * STR;           // 64*76
    uint32_t* Ps  = sm + 128 * STR;          // 128*76
    uint32_t* Qhi = sm;                      // overlay
    uint32_t* Qlo = sm + 128 * STR;          // overlay

    const int qt  = (gridDim.x - 1) - blockIdx.x;   // heavy tiles first
    const int h   = blockIdx.y;
    const int b   = blockIdx.z;
    const int tid = threadIdx.x;
    const int lane = tid & 31;
    const int wid  = tid >> 5;
    const int gid  = lane >> 2;
    const int tig  = lane & 3;
    const int q0   = qt * 128;
    const int wrow = wid * 16;
    const size_t rowbase = (size_t)b * SLEN;

    // ---- Stage Q tile (scaled by 1/8, hi/lo tf32 split) ----
    #pragma unroll
    for (int it = 0; it < 8; it++) {
        const int idx = it * 256 + tid;
        const int r = idx >> 4, c4 = idx & 15;
        const float* qp = qkv + (rowbase + q0 + r) * 3072 + h * 64 + c4 * 4;
        const float4 v = *reinterpret_cast<const float4*>(qp);
        const float f[4] = {v.x * 0.125f, v.y * 0.125f, v.z * 0.125f, v.w * 0.125f};
        #pragma unroll
        for (int j = 0; j < 4; j++) {
            const uint32_t hi = f2tf32(f[j]);
            Qhi[r * STR + c4 * 4 + j] = hi;
            Qlo[r * STR + c4 * 4 + j] = f2tf32(f[j] - __uint_as_float(hi));
        }
    }
    __syncthreads();

    uint32_t qh[8][4], ql[8][4];
    #pragma unroll
    for (int kk = 0; kk < 8; kk++) {
        const int ba = (wrow + gid) * STR + kk * 8;
        const int bb = (wrow + gid + 8) * STR + kk * 8;
        qh[kk][0] = Qhi[ba + tig];     qh[kk][1] = Qhi[bb + tig];
        qh[kk][2] = Qhi[ba + tig + 4]; qh[kk][3] = Qhi[bb + tig + 4];
        ql[kk][0] = Qlo[ba + tig];     ql[kk][1] = Qlo[bb + tig];
        ql[kk][2] = Qlo[ba + tig + 4]; ql[kk][3] = Qlo[bb + tig + 4];
    }

    float oacc[8][4];
    #pragma unroll
    for (int nf = 0; nf < 8; nf++)
        #pragma unroll
        for (int e = 0; e < 4; e++) oacc[nf][e] = 0.f;
    float m0 = -INFINITY, m1 = -INFINITY, l0 = 0.f, l1 = 0.f;

    const int row0g = q0 + wrow + gid;
    const int row1g = row0g + 8;
    const int kend  = q0 + 128;

    for (int kb = 0; kb < kend; kb += 64) {
        __syncthreads();   // protect K/V/P (and Q staging on first iter)

        // ---- load K/V chunk: 64 rows x 64 dims (K single tf32) ----
        #pragma unroll
        for (int it = 0; it < 4; it++) {
            const int idx = it * 256 + tid;
            const int r = idx >> 4, c4 = idx & 15;
            const float* kp = qkv + (rowbase + kb + r) * 3072 + N_EMBED + h * 64 + c4 * 4;
            const float4 kv = *reinterpret_cast<const float4*>(kp);
            const float4 vv = *reinterpret_cast<const float4*>(kp + N_EMBED);
            uint32_t* kd = &Kh[r * STR + c4 * 4];
            uint32_t* vd = &Vs[r * STR + c4 * 4];
            kd[0] = f2tf32(kv.x); kd[1] = f2tf32(kv.y);
            kd[2] = f2tf32(kv.z); kd[3] = f2tf32(kv.w);
            vd[0] = f2tf32(vv.x); vd[1] = f2tf32(vv.y);
            vd[2] = f2tf32(vv.z); vd[3] = f2tf32(vv.w);
        }
        __syncthreads();

        // ---- S = Q K^T (2-term split: qh*k + ql*k) ----
        float sacc[8][4];
        #pragma unroll
        for (int nf = 0; nf < 8; nf++)
            #pragma unroll
            for (int e = 0; e < 4; e++) sacc[nf][e] = 0.f;

        #pragma unroll
        for (int kk = 0; kk < 8; kk++) {
            #pragma unroll
            for (int nf = 0; nf < 8; nf++) {
                const int kr = (nf * 8 + gid) * STR + kk * 8;
                uint32_t bh[2];
                bh[0] = Kh[kr + tig]; bh[1] = Kh[kr + tig + 4];
                mma_tf32(sacc[nf], qh[kk], bh);
                mma_tf32(sacc[nf], ql[kk], bh);
            }
        }

        // ---- causal mask (diagonal chunks only) ----
        if (kb + 63 > q0 + wrow) {
            #pragma unroll
            for (int nf = 0; nf < 8; nf++) {
                const int c = kb + nf * 8 + tig * 2;
                if (c     > row0g) sacc[nf][0] = -INFINITY;
                if (c + 1 > row0g) sacc[nf][1] = -INFINITY;
                if (c     > row1g) sacc[nf][2] = -INFINITY;
                if (c + 1 > row1g) sacc[nf][3] = -INFINITY;
            }
        }

        // ---- online softmax ----
        float mx0 = -INFINITY, mx1 = -INFINITY;
        #pragma unroll
        for (int nf = 0; nf < 8; nf++) {
            mx0 = fmaxf(mx0, fmaxf(sacc[nf][0], sacc[nf][1]));
            mx1 = fmaxf(mx1, fmaxf(sacc[nf][2], sacc[nf][3]));
        }
        mx0 = fmaxf(mx0, __shfl_xor_sync(0xffffffff, mx0, 1));
        mx0 = fmaxf(mx0, __shfl_xor_sync(0xffffffff, mx0, 2));
        mx1 = fmaxf(mx1, __shfl_xor_sync(0xffffffff, mx1, 1));
        mx1 = fmaxf(mx1, __shfl_xor_sync(0xffffffff, mx1, 2));

        const float mn0 = fmaxf(m0, mx0);
        const float mn1 = fmaxf(m1, mx1);
        const float a0 = __expf(m0 - mn0);
        const float a1 = __expf(m1 - mn1);
        m0 = mn0; m1 = mn1;

        float rs0 = 0.f, rs1 = 0.f;
        #pragma unroll
        for (int nf = 0; nf < 8; nf++) {
            const float p0 = __expf(sacc[nf][0] - m0);
            const float p1 = __expf(sacc[nf][1] - m0);
            const float p2 = __expf(sacc[nf][2] - m1);
            const float p3 = __expf(sacc[nf][3] - m1);
            rs0 += p0 + p1; rs1 += p2 + p3;
            uint2 u0; u0.x = f2tf32(p0); u0.y = f2tf32(p1);
            uint2 u1; u1.x = f2tf32(p2); u1.y = f2tf32(p3);
            *reinterpret_cast<uint2*>(&Ps[(wrow + gid)     * STR + nf * 8 + 2 * tig]) = u0;
            *reinterpret_cast<uint2*>(&Ps[(wrow + gid + 8) * STR + nf * 8 + 2 * tig]) = u1;
        }
        rs0 += __shfl_xor_sync(0xffffffff, rs0, 1);
        rs0 += __shfl_xor_sync(0xffffffff, rs0, 2);
        rs1 += __shfl_xor_sync(0xffffffff, rs1, 1);
        rs1 += __shfl_xor_sync(0xffffffff, rs1, 2);
        l0 = l0 * a0 + rs0;
        l1 = l1 * a1 + rs1;

        #pragma unroll
        for (int nf = 0; nf < 8; nf++) {
            oacc[nf][0] *= a0; oacc[nf][1] *= a0;
            oacc[nf][2] *= a1; oacc[nf][3] *= a1;
        }

        __syncwarp();   // Ps rows warp-private: order stores before loads

        // ---- O += P V ----
        #pragma unroll
        for (int kk = 0; kk < 8; kk++) {
            uint32_t a[4];
            const int pa = (wrow + gid) * STR + kk * 8;
            const int pb = (wrow + gid + 8) * STR + kk * 8;
            a[0] = Ps[pa + tig];     a[1] = Ps[pb + tig];
            a[2] = Ps[pa + tig + 4]; a[3] = Ps[pb + tig + 4];
            #pragma unroll
            for (int nf = 0; nf < 8; nf++) {
                uint32_t bv[2];
                bv[0] = Vs[(kk * 8 + tig)     * STR + nf * 8 + gid];
                bv[1] = Vs[(kk * 8 + tig + 4) * STR + nf * 8 + gid];
                mma_tf32(oacc[nf], a, bv);
            }
        }
    }

    const float inv0 = 1.f / l0;
    const float inv1 = 1.f / l1;
    float* yp0 = y + (rowbase + row0g) * N_EMBED + h * 64;
    float* yp1 = y + (rowbase + row1g) * N_EMBED + h * 64;
    #pragma unroll
    for (int nf = 0; nf < 8; nf++) {
        float2 v0, v1;
        v0.x = oacc[nf][0] * inv0; v0.y = oacc[nf][1] * inv0;
        v1.x = oacc[nf][2] * inv1; v1.y = oacc[nf][3] * inv1;
        *reinterpret_cast<float2*>(yp0 + nf * 8 + 2 * tig) = v0;
        *reinterpret_cast<float2*>(yp1 + nf * 8 + 2 * tig) = v1;
    }
}

// ---------------------------------------------------------------------------
// kernel_launch
// ---------------------------------------------------------------------------
extern "C" void kernel_launch(void* const* d_in, const int* in_sizes, int n_in,
                              void* d_out, int out_size) {
    const float* x      = (const float*)d_in[0];
    const float* W_attn = (const float*)d_in[1];
    const float* b_attn = (const float*)d_in[2];
    const float* W_proj = (const float*)d_in[3];
    const float* b_proj = (const float*)d_in[4];
    float* out = (float*)d_out;

    float* qkv = nullptr; float* yb = nullptr;
    cudaGetSymbolAddress((void**)&qkv, g_qkv);
    cudaGetSymbolAddress((void**)&yb,  g_y);

    cudaFuncSetAttribute(mma_gemm_kernel,
                         cudaFuncAttributeMaxDynamicSharedMemorySize, G_SMEM_BYTES);
    cudaFuncSetAttribute(flash_attn_mma_kernel,
                         cudaFuncAttributeMaxDynamicSharedMemorySize, FA_SMEM_BYTES);

    // 1) QKV GEMM (tf32 mma.sync, 64x64 warp tiles)
    {
        dim3 grid(3 * N_EMBED / 128, MROWS / 256);
        mma_gemm_kernel<<<grid, 256, G_SMEM_BYTES>>>(x, W_attn, b_attn, qkv,
                                                     MROWS, 3 * N_EMBED, N_EMBED);
    }
    // 2) Causal flash attention (tf32 mma.sync, 2-term QK)
    {
        dim3 grid(SLEN / 128, NHEADS, BATCH);
        flash_attn_mma_kernel<<<grid, 256, FA_SMEM_BYTES>>>(qkv, yb);
    }
    // 3) Output projection
    {
        dim3 grid(N_EMBED / 128, MROWS / 256);
        mma_gemm_kernel<<<grid, 256, G_SMEM_BYTES>>>(yb, W_proj, b_proj, out,
                                                     MROWS, N_EMBED, N_EMBED);
    }
}

// round 7
// speedup vs baseline: 1.2356x; 1.1729x over previous
#include <cuda_runtime.h>
#include <math.h>
#include <stdint.h>

#define N_EMBED 1024
#define SLEN    2048
#define BATCH   4
#define NHEADS  16
#define HDIM    64
#define MROWS   (BATCH * SLEN)        // 8192

// Scratch (device globals: allocation-free rule)
__device__ float g_qkv[(size_t)MROWS * 3 * N_EMBED];  // [8192, 3072]
__device__ float g_y[(size_t)MROWS * N_EMBED];        // [8192, 1024]

// ---------------------------------------------------------------------------
// Helpers
// ---------------------------------------------------------------------------
__device__ __forceinline__ uint32_t f2tf32(float f) {
    uint32_t r;
    asm("cvt.rna.tf32.f32 %0, %1;" : "=r"(r) : "f"(f));
    return r;
}
__device__ __forceinline__ void mma_tf32(float d[4], const uint32_t a[4], const uint32_t b[2]) {
    asm volatile(
        "mma.sync.aligned.m16n8k8.row.col.f32.tf32.tf32.f32 "
        "{%0,%1,%2,%3}, {%4,%5,%6,%7}, {%8,%9}, {%0,%1,%2,%3};"
        : "+f"(d[0]), "+f"(d[1]), "+f"(d[2]), "+f"(d[3])
        : "r"(a[0]), "r"(a[1]), "r"(a[2]), "r"(a[3]), "r"(b[0]), "r"(b[1]));
}

// ---------------------------------------------------------------------------
// tf32 mma.sync GEMM v4: C[M,N] = A[M,K] @ B[K,N] + bias[N]
// BM=BN=128, BK=16; 128 threads = 4 warps (2x2), warp tile 64x64.
// Reg-staged double buffer (cvt at store), 2 CTAs/SM.
// Dynamic smem: 2*(128*20 + 16*136) words = 37888 bytes.
// ---------------------------------------------------------------------------
#define G_AS 20
#define G_BS 136
#define G_ASTG (128 * G_AS)
#define G_BSTG (16 * G_BS)
#define G_SMEM_BYTES ((2 * (G_ASTG + G_BSTG)) * 4)

__global__ __launch_bounds__(128, 2)
void mma_gemm_kernel(const float* __restrict__ A, const float* __restrict__ B,
                     const float* __restrict__ bias, float* __restrict__ C,
                     int M, int N, int K) {
    extern __shared__ uint32_t gsm[];
    uint32_t* Asm = gsm;                    // [2][128*20]
    uint32_t* Bsm = gsm + 2 * G_ASTG;       // [2][16*136]

    const int tid   = threadIdx.x;
    const int lane  = tid & 31;
    const int wid   = tid >> 5;           // 0..3
    const int gid   = lane >> 2;
    const int tig   = lane & 3;
    const int warpM = wid >> 1;           // 0..1 -> 64 rows
    const int warpN = wid & 1;            // 0..1 -> 64 cols
    const int row0  = blockIdx.y * 128;
    const int col0  = blockIdx.x * 128;

    float acc[4][8][4];
    #pragma unroll
    for (int i = 0; i < 4; i++)
        #pragma unroll
        for (int j = 0; j < 8; j++)
            #pragma unroll
            for (int r = 0; r < 4; r++) acc[i][j][r] = 0.f;

    float4 av[4], bv[4];
    const int NT = K / 16;

    const int arow = tid >> 2, ac = (tid & 3) * 4;   // rows + i*32
    const int brow = tid >> 5, bc = (tid & 31) * 4;  // rows + i*4

    auto load_tile = [&](int kt) {
        #pragma unroll
        for (int i = 0; i < 4; i++)
            av[i] = *reinterpret_cast<const float4*>(
                A + (size_t)(row0 + arow + i * 32) * K + kt * 16 + ac);
        #pragma unroll
        for (int i = 0; i < 4; i++)
            bv[i] = *reinterpret_cast<const float4*>(
                B + (size_t)(kt * 16 + brow + i * 4) * N + col0 + bc);
    };
    auto store_tile = [&](int buf) {
        uint32_t* Ab = Asm + buf * G_ASTG;
        uint32_t* Bb = Bsm + buf * G_BSTG;
        #pragma unroll
        for (int i = 0; i < 4; i++) {
            uint32_t* ap = &Ab[(arow + i * 32) * G_AS + ac];
            ap[0] = f2tf32(av[i].x); ap[1] = f2tf32(av[i].y);
            ap[2] = f2tf32(av[i].z); ap[3] = f2tf32(av[i].w);
        }
        #pragma unroll
        for (int i = 0; i < 4; i++) {
            uint32_t* bp = &Bb[(brow + i * 4) * G_BS + bc];
            bp[0] = f2tf32(bv[i].x); bp[1] = f2tf32(bv[i].y);
            bp[2] = f2tf32(bv[i].z); bp[3] = f2tf32(bv[i].w);
        }
    };
    auto compute = [&](int buf) {
        const uint32_t* As = Asm + buf * G_ASTG;
        const uint32_t* Bs = Bsm + buf * G_BSTG;
        #pragma unroll
        for (int ks = 0; ks < 2; ks++) {
            const int kb = ks * 8;
            uint32_t a[4][4], b[8][2];
            #pragma unroll
            for (int mf = 0; mf < 4; mf++) {
                const int r = warpM * 64 + mf * 16;
                a[mf][0] = As[(r + gid)     * G_AS + kb + tig];
                a[mf][1] = As[(r + gid + 8) * G_AS + kb + tig];
                a[mf][2] = As[(r + gid)     * G_AS + kb + tig + 4];
                a[mf][3] = As[(r + gid + 8) * G_AS + kb + tig + 4];
            }
            #pragma unroll
            for (int nf = 0; nf < 8; nf++) {
                const int c = warpN * 64 + nf * 8 + gid;
                b[nf][0] = Bs[(kb + tig)     * G_BS + c];
                b[nf][1] = Bs[(kb + tig + 4) * G_BS + c];
            }
            #pragma unroll
            for (int mf = 0; mf < 4; mf++)
                #pragma unroll
                for (int nf = 0; nf < 8; nf++)
                    mma_tf32(acc[mf][nf], a[mf], b[nf]);
        }
    };

    load_tile(0);
    store_tile(0);
    __syncthreads();

    for (int kt = 0; kt < NT; kt++) {
        const int cur = kt & 1;
        const bool more = (kt + 1) < NT;
        if (more) load_tile(kt + 1);
        compute(cur);
        if (more) store_tile(cur ^ 1);
        __syncthreads();
    }

    // Epilogue: add bias, store fp32
    #pragma unroll
    for (int mf = 0; mf < 4; mf++) {
        const size_t rbase = (size_t)row0 + warpM * 64 + mf * 16 + gid;
        #pragma unroll
        for (int nf = 0; nf < 8; nf++) {
            const int col = col0 + warpN * 64 + nf * 8 + tig * 2;
            const float2 bz = *reinterpret_cast<const float2*>(bias + col);
            float2 v0, v1;
            v0.x = acc[mf][nf][0] + bz.x; v0.y = acc[mf][nf][1] + bz.y;
            v1.x = acc[mf][nf][2] + bz.x; v1.y = acc[mf][nf][3] + bz.y;
            *reinterpret_cast<float2*>(C + rbase * N + col)       = v0;
            *reinterpret_cast<float2*>(C + (rbase + 8) * N + col) = v1;
        }
    }
}

// ---------------------------------------------------------------------------
// Flash attention, tf32 mma.sync, 2-term QK split, K/V register prefetch.
// CTA = 128 q-rows x head x batch; 8 warps x 16 q-rows; 64-key chunks.
// SMEM words (stride 76): Kh[64*76] Vs[64*76] Ps[128*76] = 256*76
// Q staging overlay: Qhi[128*76] Qlo[128*76] (same region).
// ---------------------------------------------------------------------------
#define STR 76
#define FA_SMEM_BYTES (256 * STR * 4)

__global__ __launch_bounds__(256)
void flash_attn_mma_kernel(const float* __restrict__ qkv, float* __restrict__ y) {
    extern __shared__ uint32_t sm[];
    uint32_t* Kh  = sm;                      // 64*76
    uint32_t* Vs  = sm + 64 * STR;           // 64*76
    uint32_t* Ps  = sm + 128 * STR;          // 128*76
    uint32_t* Qhi = sm;                      // overlay
    uint32_t* Qlo = sm + 128 * STR;          // overlay

    const int qt  = (gridDim.x - 1) - blockIdx.x;   // heavy tiles first
    const int h   = blockIdx.y;
    const int b   = blockIdx.z;
    const int tid = threadIdx.x;
    const int lane = tid & 31;
    const int wid  = tid >> 5;
    const int gid  = lane >> 2;
    const int tig  = lane & 3;
    const int q0   = qt * 128;
    const int wrow = wid * 16;
    const size_t rowbase = (size_t)b * SLEN;

    // ---- Stage Q tile (scaled by 1/8, hi/lo tf32 split) ----
    #pragma unroll
    for (int it = 0; it < 8; it++) {
        const int idx = it * 256 + tid;
        const int r = idx >> 4, c4 = idx & 15;
        const float* qp = qkv + (rowbase + q0 + r) * 3072 + h * 64 + c4 * 4;
        const float4 v = *reinterpret_cast<const float4*>(qp);
        const float f[4] = {v.x * 0.125f, v.y * 0.125f, v.z * 0.125f, v.w * 0.125f};
        #pragma unroll
        for (int j = 0; j < 4; j++) {
            const uint32_t hi = f2tf32(f[j]);
            Qhi[r * STR + c4 * 4 + j] = hi;
            Qlo[r * STR + c4 * 4 + j] = f2tf32(f[j] - __uint_as_float(hi));
        }
    }
    __syncthreads();

    uint32_t qh[8][4], ql[8][4];
    #pragma unroll
    for (int kk = 0; kk < 8; kk++) {
        const int ba = (wrow + gid) * STR + kk * 8;
        const int bb = (wrow + gid + 8) * STR + kk * 8;
        qh[kk][0] = Qhi[ba + tig];     qh[kk][1] = Qhi[bb + tig];
        qh[kk][2] = Qhi[ba + tig + 4]; qh[kk][3] = Qhi[bb + tig + 4];
        ql[kk][0] = Qlo[ba + tig];     ql[kk][1] = Qlo[bb + tig];
        ql[kk][2] = Qlo[ba + tig + 4]; ql[kk][3] = Qlo[bb + tig + 4];
    }

    float oacc[8][4];
    #pragma unroll
    for (int nf = 0; nf < 8; nf++)
        #pragma unroll
        for (int e = 0; e < 4; e++) oacc[nf][e] = 0.f;
    float m0 = -INFINITY, m1 = -INFINITY, l0 = 0.f, l1 = 0.f;

    const int row0g = q0 + wrow + gid;
    const int row1g = row0g + 8;
    const int kend  = q0 + 128;

    // ---- K/V register prefetch (chunk 0) ----
    float4 kpre[4], vpre[4];
    auto ldg_chunk = [&](int kb) {
        #pragma unroll
        for (int it = 0; it < 4; it++) {
            const int idx = it * 256 + tid;
            const int r = idx >> 4, c4 = idx & 15;
            const float* kp = qkv + (rowbase + kb + r) * 3072 + N_EMBED + h * 64 + c4 * 4;
            kpre[it] = *reinterpret_cast<const float4*>(kp);
            vpre[it] = *reinterpret_cast<const float4*>(kp + N_EMBED);
        }
    };
    ldg_chunk(0);

    for (int kb = 0; kb < kend; kb += 64) {
        __syncthreads();   // protect K/V/P writers vs prev readers (and Q staging, iter 0)

        // ---- STS prefetched chunk (tf32 cvt), then issue next LDG ----
        #pragma unroll
        for (int it = 0; it < 4; it++) {
            const int idx = it * 256 + tid;
            const int r = idx >> 4, c4 = idx & 15;
            uint32_t* kd = &Kh[r * STR + c4 * 4];
            uint32_t* vd = &Vs[r * STR + c4 * 4];
            kd[0] = f2tf32(kpre[it].x); kd[1] = f2tf32(kpre[it].y);
            kd[2] = f2tf32(kpre[it].z); kd[3] = f2tf32(kpre[it].w);
            vd[0] = f2tf32(vpre[it].x); vd[1] = f2tf32(vpre[it].y);
            vd[2] = f2tf32(vpre[it].z); vd[3] = f2tf32(vpre[it].w);
        }
        if (kb + 64 < kend) ldg_chunk(kb + 64);
        __syncthreads();

        // ---- S = Q K^T (2-term split: qh*k + ql*k) ----
        float sacc[8][4];
        #pragma unroll
        for (int nf = 0; nf < 8; nf++)
            #pragma unroll
            for (int e = 0; e < 4; e++) sacc[nf][e] = 0.f;

        #pragma unroll
        for (int kk = 0; kk < 8; kk++) {
            #pragma unroll
            for (int nf = 0; nf < 8; nf++) {
                const int kr = (nf * 8 + gid) * STR + kk * 8;
                uint32_t bh[2];
                bh[0] = Kh[kr + tig]; bh[1] = Kh[kr + tig + 4];
                mma_tf32(sacc[nf], qh[kk], bh);
                mma_tf32(sacc[nf], ql[kk], bh);
            }
        }

        // ---- causal mask (diagonal chunks only) ----
        if (kb + 63 > q0 + wrow) {
            #pragma unroll
            for (int nf = 0; nf < 8; nf++) {
                const int c = kb + nf * 8 + tig * 2;
                if (c     > row0g) sacc[nf][0] = -INFINITY;
                if (c + 1 > row0g) sacc[nf][1] = -INFINITY;
                if (c     > row1g) sacc[nf][2] = -INFINITY;
                if (c + 1 > row1g) sacc[nf][3] = -INFINITY;
            }
        }

        // ---- online softmax ----
        float mx0 = -INFINITY, mx1 = -INFINITY;
        #pragma unroll
        for (int nf = 0; nf < 8; nf++) {
            mx0 = fmaxf(mx0, fmaxf(sacc[nf][0], sacc[nf][1]));
            mx1 = fmaxf(mx1, fmaxf(sacc[nf][2], sacc[nf][3]));
        }
        mx0 = fmaxf(mx0, __shfl_xor_sync(0xffffffff, mx0, 1));
        mx0 = fmaxf(mx0, __shfl_xor_sync(0xffffffff, mx0, 2));
        mx1 = fmaxf(mx1, __shfl_xor_sync(0xffffffff, mx1, 1));
        mx1 = fmaxf(mx1, __shfl_xor_sync(0xffffffff, mx1, 2));

        const float mn0 = fmaxf(m0, mx0);
        const float mn1 = fmaxf(m1, mx1);
        const float a0 = __expf(m0 - mn0);
        const float a1 = __expf(m1 - mn1);
        m0 = mn0; m1 = mn1;

        float rs0 = 0.f, rs1 = 0.f;
        #pragma unroll
        for (int nf = 0; nf < 8; nf++) {
            const float p0 = __expf(sacc[nf][0] - m0);
            const float p1 = __expf(sacc[nf][1] - m0);
            const float p2 = __expf(sacc[nf][2] - m1);
            const float p3 = __expf(sacc[nf][3] - m1);
            rs0 += p0 + p1; rs1 += p2 + p3;
            uint2 u0; u0.x = f2tf32(p0); u0.y = f2tf32(p1);
            uint2 u1; u1.x = f2tf32(p2); u1.y = f2tf32(p3);
            *reinterpret_cast<uint2*>(&Ps[(wrow + gid)     * STR + nf * 8 + 2 * tig]) = u0;
            *reinterpret_cast<uint2*>(&Ps[(wrow + gid + 8) * STR + nf * 8 + 2 * tig]) = u1;
        }
        rs0 += __shfl_xor_sync(0xffffffff, rs0, 1);
        rs0 += __shfl_xor_sync(0xffffffff, rs0, 2);
        rs1 += __shfl_xor_sync(0xffffffff, rs1, 1);
        rs1 += __shfl_xor_sync(0xffffffff, rs1, 2);
        l0 = l0 * a0 + rs0;
        l1 = l1 * a1 + rs1;

        #pragma unroll
        for (int nf = 0; nf < 8; nf++) {
            oacc[nf][0] *= a0; oacc[nf][1] *= a0;
            oacc[nf][2] *= a1; oacc[nf][3] *= a1;
        }

        __syncwarp();   // Ps rows warp-private: order stores before loads

        // ---- O += P V ----
        #pragma unroll
        for (int kk = 0; kk < 8; kk++) {
            uint32_t a[4];
            const int pa = (wrow + gid) * STR + kk * 8;
            const int pb = (wrow + gid + 8) * STR + kk * 8;
            a[0] = Ps[pa + tig];     a[1] = Ps[pb + tig];
            a[2] = Ps[pa + tig + 4]; a[3] = Ps[pb + tig + 4];
            #pragma unroll
            for (int nf = 0; nf < 8; nf++) {
                uint32_t bv[2];
                bv[0] = Vs[(kk * 8 + tig)     * STR + nf * 8 + gid];
                bv[1] = Vs[(kk * 8 + tig + 4) * STR + nf * 8 + gid];
                mma_tf32(oacc[nf], a, bv);
            }
        }
    }

    const float inv0 = 1.f / l0;
    const float inv1 = 1.f / l1;
    float* yp0 = y + (rowbase + row0g) * N_EMBED + h * 64;
    float* yp1 = y + (rowbase + row1g) * N_EMBED + h * 64;
    #pragma unroll
    for (int nf = 0; nf < 8; nf++) {
        float2 v0, v1;
        v0.x = oacc[nf][0] * inv0; v0.y = oacc[nf][1] * inv0;
        v1.x = oacc[nf][2] * inv1; v1.y = oacc[nf][3] * inv1;
        *reinterpret_cast<float2*>(yp0 + nf * 8 + 2 * tig) = v0;
        *reinterpret_cast<float2*>(yp1 + nf * 8 + 2 * tig) = v1;
    }
}

// ---------------------------------------------------------------------------
// kernel_launch
// ---------------------------------------------------------------------------
extern "C" void kernel_launch(void* const* d_in, const int* in_sizes, int n_in,
                              void* d_out, int out_size) {
    const float* x      = (const float*)d_in[0];
    const float* W_attn = (const float*)d_in[1];
    const float* b_attn = (const float*)d_in[2];
    const float* W_proj = (const float*)d_in[3];
    const float* b_proj = (const float*)d_in[4];
    float* out = (float*)d_out;

    float* qkv = nullptr; float* yb = nullptr;
    cudaGetSymbolAddress((void**)&qkv, g_qkv);
    cudaGetSymbolAddress((void**)&yb,  g_y);

    cudaFuncSetAttribute(mma_gemm_kernel,
                         cudaFuncAttributeMaxDynamicSharedMemorySize, G_SMEM_BYTES);
    cudaFuncSetAttribute(flash_attn_mma_kernel,
                         cudaFuncAttributeMaxDynamicSharedMemorySize, FA_SMEM_BYTES);

    // 1) QKV GEMM (tf32 mma.sync, 64x64 warp tiles, 2 CTAs/SM)
    {
        dim3 grid(3 * N_EMBED / 128, MROWS / 128);
        mma_gemm_kernel<<<grid, 128, G_SMEM_BYTES>>>(x, W_attn, b_attn, qkv,
                                                     MROWS, 3 * N_EMBED, N_EMBED);
    }
    // 2) Causal flash attention (tf32 mma.sync, 2-term QK, LDG prefetch)
    {
        dim3 grid(SLEN / 128, NHEADS, BATCH);
        flash_attn_mma_kernel<<<grid, 256, FA_SMEM_BYTES>>>(qkv, yb);
    }
    // 3) Output projection
    {
        dim3 grid(N_EMBED / 128, MROWS / 128);
        mma_gemm_kernel<<<grid, 128, G_SMEM_BYTES>>>(yb, W_proj, b_proj, out,
                                                     MROWS, N_EMBED, N_EMBED);
    }
}

// round 8
// speedup vs baseline: 1.3080x; 1.0586x over previous
#include <cuda_runtime.h>
#include <math.h>
#include <stdint.h>

#define N_EMBED 1024
#define SLEN    2048
#define BATCH   4
#define NHEADS  16
#define HDIM    64
#define MROWS   (BATCH * SLEN)        // 8192

// Scratch (device globals: allocation-free rule)
__device__ float g_qkv[(size_t)MROWS * 3 * N_EMBED];  // [8192, 3072] fp32
__device__ float g_y[(size_t)MROWS * N_EMBED];        // [8192, 1024] tf32 bits
__device__ float g_cvt[(size_t)MROWS * N_EMBED        // x_tf32
                     + (size_t)N_EMBED * 3 * N_EMBED  // Wattn_tf32
                     + (size_t)N_EMBED * N_EMBED];    // Wproj_tf32

// ---------------------------------------------------------------------------
// Helpers
// ---------------------------------------------------------------------------
__device__ __forceinline__ uint32_t f2tf32(float f) {
    uint32_t r;
    asm("cvt.rna.tf32.f32 %0, %1;" : "=r"(r) : "f"(f));
    return r;
}
__device__ __forceinline__ void mma_tf32(float d[4], const uint32_t a[4], const uint32_t b[2]) {
    asm volatile(
        "mma.sync.aligned.m16n8k8.row.col.f32.tf32.tf32.f32 "
        "{%0,%1,%2,%3}, {%4,%5,%6,%7}, {%8,%9}, {%0,%1,%2,%3};"
        : "+f"(d[0]), "+f"(d[1]), "+f"(d[2]), "+f"(d[3])
        : "r"(a[0]), "r"(a[1]), "r"(a[2]), "r"(a[3]), "r"(b[0]), "r"(b[1]));
}
__device__ __forceinline__ uint32_t smem_u32(const void* p) {
    uint32_t a;
    asm("{ .reg .u64 t; cvta.to.shared.u64 t, %1; cvt.u32.u64 %0, t; }" : "=r"(a) : "l"(p));
    return a;
}
__device__ __forceinline__ void cp_async16(uint32_t saddr, const void* g) {
    asm volatile("cp.async.cg.shared.global [%0], [%1], 16;" :: "r"(saddr), "l"(g));
}
#define CP_COMMIT()  asm volatile("cp.async.commit_group;" ::: "memory")
#define CP_WAIT(n)   asm volatile("cp.async.wait_group %0;" :: "n"(n) : "memory")

// ---------------------------------------------------------------------------
// Elementwise fp32 -> tf32-bit-pattern conversion (vectorized, grid-stride).
// ---------------------------------------------------------------------------
__global__ __launch_bounds__(256)
void cvt_tf32_kernel(const float* __restrict__ in, float* __restrict__ out, int n) {
    const int stride = gridDim.x * blockDim.x * 4;
    for (int i = (blockIdx.x * blockDim.x + threadIdx.x) * 4; i < n; i += stride) {
        float4 v = *reinterpret_cast<const float4*>(in + i);
        float4 o;
        o.x = __uint_as_float(f2tf32(v.x));
        o.y = __uint_as_float(f2tf32(v.y));
        o.z = __uint_as_float(f2tf32(v.z));
        o.w = __uint_as_float(f2tf32(v.w));
        *reinterpret_cast<float4*>(out + i) = o;
    }
}

// ---------------------------------------------------------------------------
// tf32 mma.sync GEMM v5: C[M,N] = A[M,K] @ B[K,N] + bias[N]
// A, B hold tf32 BIT PATTERNS already (no cvt in kernel).
// BM=BN=128, BK=16; 128 threads = 4 warps (2x2), warp tile 64x64.
// 4-stage cp.async.cg pipeline; 2 CTAs/SM.
// smem/stage: 128*20 + 16*136 = 4736 words; 4 stages = 75776 bytes.
// ---------------------------------------------------------------------------
#define G_AS 20
#define G_BS 136
#define G_ASTG (128 * G_AS)
#define G_BSTG (16 * G_BS)
#define G_STG_WORDS (G_ASTG + G_BSTG)
#define G_SMEM_BYTES (4 * G_STG_WORDS * 4)

__global__ __launch_bounds__(128, 2)
void mma_gemm_kernel(const float* __restrict__ A, const float* __restrict__ B,
                     const float* __restrict__ bias, float* __restrict__ C,
                     int M, int N, int K) {
    extern __shared__ uint32_t gsm[];

    const int tid   = threadIdx.x;
    const int lane  = tid & 31;
    const int wid   = tid >> 5;           // 0..3
    const int gid   = lane >> 2;
    const int tig   = lane & 3;
    const int warpM = wid >> 1;           // 0..1 -> 64 rows
    const int warpN = wid & 1;            // 0..1 -> 64 cols
    const int row0  = blockIdx.y * 128;
    const int col0  = blockIdx.x * 128;

    const uint32_t uS = smem_u32(gsm);

    // Per-stage load mapping: A 128x16 (512 float4), B 16x128 (512 float4),
    // 128 threads -> 4 chunks each.
    const int arow = tid >> 2, ac = (tid & 3) * 4;   // A rows + i*32
    const int brow = tid >> 5, bc = (tid & 31) * 4;  // B rows + i*4

    auto issue = [&](int kt, int stg) {
        const float* Ag = A + (size_t)row0 * K + kt * 16;
        const float* Bg = B + (size_t)(kt * 16) * N + col0;
        const uint32_t sa = uS + (uint32_t)(stg * G_STG_WORDS) * 4;
        const uint32_t sb = sa + (uint32_t)G_ASTG * 4;
        #pragma unroll
        for (int i = 0; i < 4; i++)
            cp_async16(sa + (uint32_t)((arow + i * 32) * G_AS + ac) * 4,
                       Ag + (size_t)(arow + i * 32) * K + ac);
        #pragma unroll
        for (int i = 0; i < 4; i++)
            cp_async16(sb + (uint32_t)((brow + i * 4) * G_BS + bc) * 4,
                       Bg + (size_t)(brow + i * 4) * N + bc);
        CP_COMMIT();
    };

    float acc[4][8][4];
    #pragma unroll
    for (int i = 0; i < 4; i++)
        #pragma unroll
        for (int j = 0; j < 8; j++)
            #pragma unroll
            for (int r = 0; r < 4; r++) acc[i][j][r] = 0.f;

    const int NT = K / 16;

    issue(0, 0); issue(1, 1); issue(2, 2);

    for (int kt = 0; kt < NT; kt++) {
        if (kt < NT - 2) { CP_WAIT(2); } else { CP_WAIT(0); }
        __syncthreads();

        const uint32_t* As = gsm + (kt & 3) * G_STG_WORDS;
        const uint32_t* Bs = As + G_ASTG;

        #pragma unroll
        for (int ks = 0; ks < 2; ks++) {
            const int kb = ks * 8;
            uint32_t a[4][4], b[8][2];
            #pragma unroll
            for (int mf = 0; mf < 4; mf++) {
                const int r = warpM * 64 + mf * 16;
                a[mf][0] = As[(r + gid)     * G_AS + kb + tig];
                a[mf][1] = As[(r + gid + 8) * G_AS + kb + tig];
                a[mf][2] = As[(r + gid)     * G_AS + kb + tig + 4];
                a[mf][3] = As[(r + gid + 8) * G_AS + kb + tig + 4];
            }
            #pragma unroll
            for (int nf = 0; nf < 8; nf++) {
                const int c = warpN * 64 + nf * 8 + gid;
                b[nf][0] = Bs[(kb + tig)     * G_BS + c];
                b[nf][1] = Bs[(kb + tig + 4) * G_BS + c];
            }
            #pragma unroll
            for (int mf = 0; mf < 4; mf++)
                #pragma unroll
                for (int nf = 0; nf < 8; nf++)
                    mma_tf32(acc[mf][nf], a[mf], b[nf]);
        }
        if (kt + 3 < NT) issue(kt + 3, (kt + 3) & 3);
    }

    // Epilogue: add bias, store fp32
    #pragma unroll
    for (int mf = 0; mf < 4; mf++) {
        const size_t rbase = (size_t)row0 + warpM * 64 + mf * 16 + gid;
        #pragma unroll
        for (int nf = 0; nf < 8; nf++) {
            const int col = col0 + warpN * 64 + nf * 8 + tig * 2;
            const float2 bz = *reinterpret_cast<const float2*>(bias + col);
            float2 v0, v1;
            v0.x = acc[mf][nf][0] + bz.x; v0.y = acc[mf][nf][1] + bz.y;
            v1.x = acc[mf][nf][2] + bz.x; v1.y = acc[mf][nf][3] + bz.y;
            *reinterpret_cast<float2*>(C + rbase * N + col)       = v0;
            *reinterpret_cast<float2*>(C + (rbase + 8) * N + col) = v1;
        }
    }
}

// ---------------------------------------------------------------------------
// Flash attention, tf32 mma.sync, 2-term QK split, K/V register prefetch.
// CTA = 64 q-rows x head x batch; 4 warps (128 thr) x 16 q-rows; 64-key chunks.
// 2 CTAs/SM. Writes y as tf32 bit patterns (consumed directly by proj GEMM).
// SMEM words (stride 76): Kh[64*76] Vs[64*76] Ps[64*76] = 192*76 (58368 B)
// Q staging overlay: Qhi[64*76] Qlo[64*76] over Kh/Vs.
// ---------------------------------------------------------------------------
#define STR 76
#define FA_SMEM_BYTES (192 * STR * 4)

__global__ __launch_bounds__(128, 2)
void flash_attn_mma_kernel(const float* __restrict__ qkv, float* __restrict__ y) {
    extern __shared__ uint32_t sm[];
    uint32_t* Kh  = sm;                      // 64*76
    uint32_t* Vs  = sm + 64 * STR;           // 64*76
    uint32_t* Ps  = sm + 128 * STR;          // 64*76
    uint32_t* Qhi = sm;                      // overlay
    uint32_t* Qlo = sm + 64 * STR;           // overlay

    const int qt  = (gridDim.x - 1) - blockIdx.x;   // heavy tiles first
    const int h   = blockIdx.y;
    const int b   = blockIdx.z;
    const int tid = threadIdx.x;
    const int lane = tid & 31;
    const int wid  = tid >> 5;     // 0..3
    const int gid  = lane >> 2;
    const int tig  = lane & 3;
    const int q0   = qt * 64;
    const int wrow = wid * 16;
    const size_t rowbase = (size_t)b * SLEN;

    // ---- Stage Q tile (scaled by 1/8, hi/lo tf32 split): 64 rows ----
    #pragma unroll
    for (int it = 0; it < 8; it++) {
        const int idx = it * 128 + tid;       // 1024 float4
        const int r = idx >> 4, c4 = idx & 15;
        const float* qp = qkv + (rowbase + q0 + r) * 3072 + h * 64 + c4 * 4;
        const float4 v = *reinterpret_cast<const float4*>(qp);
        const float f[4] = {v.x * 0.125f, v.y * 0.125f, v.z * 0.125f, v.w * 0.125f};
        #pragma unroll
        for (int j = 0; j < 4; j++) {
            const uint32_t hi = f2tf32(f[j]);
            Qhi[r * STR + c4 * 4 + j] = hi;
            Qlo[r * STR + c4 * 4 + j] = f2tf32(f[j] - __uint_as_float(hi));
        }
    }
    __syncthreads();

    uint32_t qh[8][4], ql[8][4];
    #pragma unroll
    for (int kk = 0; kk < 8; kk++) {
        const int ba = (wrow + gid) * STR + kk * 8;
        const int bb = (wrow + gid + 8) * STR + kk * 8;
        qh[kk][0] = Qhi[ba + tig];     qh[kk][1] = Qhi[bb + tig];
        qh[kk][2] = Qhi[ba + tig + 4]; qh[kk][3] = Qhi[bb + tig + 4];
        ql[kk][0] = Qlo[ba + tig];     ql[kk][1] = Qlo[bb + tig];
        ql[kk][2] = Qlo[ba + tig + 4]; ql[kk][3] = Qlo[bb + tig + 4];
    }

    float oacc[8][4];
    #pragma unroll
    for (int nf = 0; nf < 8; nf++)
        #pragma unroll
        for (int e = 0; e < 4; e++) oacc[nf][e] = 0.f;
    float m0 = -INFINITY, m1 = -INFINITY, l0 = 0.f, l1 = 0.f;

    const int row0g = q0 + wrow + gid;
    const int row1g = row0g + 8;
    const int kend  = q0 + 64;

    // ---- K/V register prefetch (chunk 0): 8 float4 pairs ----
    float4 kpre[8], vpre[8];
    auto ldg_chunk = [&](int kb) {
        #pragma unroll
        for (int it = 0; it < 8; it++) {
            const int idx = it * 128 + tid;
            const int r = idx >> 4, c4 = idx & 15;
            const float* kp = qkv + (rowbase + kb + r) * 3072 + N_EMBED + h * 64 + c4 * 4;
            kpre[it] = *reinterpret_cast<const float4*>(kp);
            vpre[it] = *reinterpret_cast<const float4*>(kp + N_EMBED);
        }
    };
    ldg_chunk(0);

    for (int kb = 0; kb < kend; kb += 64) {
        __syncthreads();   // protect K/V/P writers vs prev readers (and Q staging, iter 0)

        // ---- STS prefetched chunk (tf32 cvt), then issue next LDG ----
        #pragma unroll
        for (int it = 0; it < 8; it++) {
            const int idx = it * 128 + tid;
            const int r = idx >> 4, c4 = idx & 15;
            uint32_t* kd = &Kh[r * STR + c4 * 4];
            uint32_t* vd = &Vs[r * STR + c4 * 4];
            kd[0] = f2tf32(kpre[it].x); kd[1] = f2tf32(kpre[it].y);
            kd[2] = f2tf32(kpre[it].z); kd[3] = f2tf32(kpre[it].w);
            vd[0] = f2tf32(vpre[it].x); vd[1] = f2tf32(vpre[it].y);
            vd[2] = f2tf32(vpre[it].z); vd[3] = f2tf32(vpre[it].w);
        }
        if (kb + 64 < kend) ldg_chunk(kb + 64);
        __syncthreads();

        // ---- S = Q K^T (2-term split: qh*k + ql*k) ----
        float sacc[8][4];
        #pragma unroll
        for (int nf = 0; nf < 8; nf++)
            #pragma unroll
            for (int e = 0; e < 4; e++) sacc[nf][e] = 0.f;

        #pragma unroll
        for (int kk = 0; kk < 8; kk++) {
            #pragma unroll
            for (int nf = 0; nf < 8; nf++) {
                const int kr = (nf * 8 + gid) * STR + kk * 8;
                uint32_t bh[2];
                bh[0] = Kh[kr + tig]; bh[1] = Kh[kr + tig + 4];
                mma_tf32(sacc[nf], qh[kk], bh);
                mma_tf32(sacc[nf], ql[kk], bh);
            }
        }

        // ---- causal mask (diagonal chunk only) ----
        if (kb + 63 > q0 + wrow) {
            #pragma unroll
            for (int nf = 0; nf < 8; nf++) {
                const int c = kb + nf * 8 + tig * 2;
                if (c     > row0g) sacc[nf][0] = -INFINITY;
                if (c + 1 > row0g) sacc[nf][1] = -INFINITY;
                if (c     > row1g) sacc[nf][2] = -INFINITY;
                if (c + 1 > row1g) sacc[nf][3] = -INFINITY;
            }
        }

        // ---- online softmax ----
        float mx0 = -INFINITY, mx1 = -INFINITY;
        #pragma unroll
        for (int nf = 0; nf < 8; nf++) {
            mx0 = fmaxf(mx0, fmaxf(sacc[nf][0], sacc[nf][1]));
            mx1 = fmaxf(mx1, fmaxf(sacc[nf][2], sacc[nf][3]));
        }
        mx0 = fmaxf(mx0, __shfl_xor_sync(0xffffffff, mx0, 1));
        mx0 = fmaxf(mx0, __shfl_xor_sync(0xffffffff, mx0, 2));
        mx1 = fmaxf(mx1, __shfl_xor_sync(0xffffffff, mx1, 1));
        mx1 = fmaxf(mx1, __shfl_xor_sync(0xffffffff, mx1, 2));

        const float mn0 = fmaxf(m0, mx0);
        const float mn1 = fmaxf(m1, mx1);
        const float a0 = __expf(m0 - mn0);
        const float a1 = __expf(m1 - mn1);
        m0 = mn0; m1 = mn1;

        float rs0 = 0.f, rs1 = 0.f;
        #pragma unroll
        for (int nf = 0; nf < 8; nf++) {
            const float p0 = __expf(sacc[nf][0] - m0);
            const float p1 = __expf(sacc[nf][1] - m0);
            const float p2 = __expf(sacc[nf][2] - m1);
            const float p3 = __expf(sacc[nf][3] - m1);
            rs0 += p0 + p1; rs1 += p2 + p3;
            uint2 u0; u0.x = f2tf32(p0); u0.y = f2tf32(p1);
            uint2 u1; u1.x = f2tf32(p2); u1.y = f2tf32(p3);
            *reinterpret_cast<uint2*>(&Ps[(wrow + gid)     * STR + nf * 8 + 2 * tig]) = u0;
            *reinterpret_cast<uint2*>(&Ps[(wrow + gid + 8) * STR + nf * 8 + 2 * tig]) = u1;
        }
        rs0 += __shfl_xor_sync(0xffffffff, rs0, 1);
        rs0 += __shfl_xor_sync(0xffffffff, rs0, 2);
        rs1 += __shfl_xor_sync(0xffffffff, rs1, 1);
        rs1 += __shfl_xor_sync(0xffffffff, rs1, 2);
        l0 = l0 * a0 + rs0;
        l1 = l1 * a1 + rs1;

        #pragma unroll
        for (int nf = 0; nf < 8; nf++) {
            oacc[nf][0] *= a0; oacc[nf][1] *= a0;
            oacc[nf][2] *= a1; oacc[nf][3] *= a1;
        }

        __syncwarp();   // Ps rows warp-private: order stores before loads

        // ---- O += P V ----
        #pragma unroll
        for (int kk = 0; kk < 8; kk++) {
            uint32_t a[4];
            const int pa = (wrow + gid) * STR + kk * 8;
            const int pb = (wrow + gid + 8) * STR + kk * 8;
            a[0] = Ps[pa + tig];     a[1] = Ps[pb + tig];
            a[2] = Ps[pa + tig + 4]; a[3] = Ps[pb + tig + 4];
            #pragma unroll
            for (int nf = 0; nf < 8; nf++) {
                uint32_t bv[2];
                bv[0] = Vs[(kk * 8 + tig)     * STR + nf * 8 + gid];
                bv[1] = Vs[(kk * 8 + tig + 4) * STR + nf * 8 + gid];
                mma_tf32(oacc[nf], a, bv);
            }
        }
    }

    // ---- epilogue: normalize, write y as tf32 BIT PATTERNS ----
    const float inv0 = 1.f / l0;
    const float inv1 = 1.f / l1;
    float* yp0 = y + (rowbase + row0g) * N_EMBED + h * 64;
    float* yp1 = y + (rowbase + row1g) * N_EMBED + h * 64;
    #pragma unroll
    for (int nf = 0; nf < 8; nf++) {
        float2 v0, v1;
        v0.x = __uint_as_float(f2tf32(oacc[nf][0] * inv0));
        v0.y = __uint_as_float(f2tf32(oacc[nf][1] * inv0));
        v1.x = __uint_as_float(f2tf32(oacc[nf][2] * inv1));
        v1.y = __uint_as_float(f2tf32(oacc[nf][3] * inv1));
        *reinterpret_cast<float2*>(yp0 + nf * 8 + 2 * tig) = v0;
        *reinterpret_cast<float2*>(yp1 + nf * 8 + 2 * tig) = v1;
    }
}

// ---------------------------------------------------------------------------
// kernel_launch
// ---------------------------------------------------------------------------
extern "C" void kernel_launch(void* const* d_in, const int* in_sizes, int n_in,
                              void* d_out, int out_size) {
    const float* x      = (const float*)d_in[0];
    const float* W_attn = (const float*)d_in[1];
    const float* b_attn = (const float*)d_in[2];
    const float* W_proj = (const float*)d_in[3];
    const float* b_proj = (const float*)d_in[4];
    float* out = (float*)d_out;

    float* qkv = nullptr; float* yb = nullptr; float* cv = nullptr;
    cudaGetSymbolAddress((void**)&qkv, g_qkv);
    cudaGetSymbolAddress((void**)&yb,  g_y);
    cudaGetSymbolAddress((void**)&cv,  g_cvt);

    float* x_t  = cv;                                          // [8192,1024]
    float* wa_t = x_t + (size_t)MROWS * N_EMBED;               // [1024,3072]
    float* wp_t = wa_t + (size_t)N_EMBED * 3 * N_EMBED;        // [1024,1024]

    cudaFuncSetAttribute(mma_gemm_kernel,
                         cudaFuncAttributeMaxDynamicSharedMemorySize, G_SMEM_BYTES);
    cudaFuncSetAttribute(flash_attn_mma_kernel,
                         cudaFuncAttributeMaxDynamicSharedMemorySize, FA_SMEM_BYTES);

    // 0) Pre-convert operands to tf32 bit patterns
    cvt_tf32_kernel<<<592, 256>>>(x,      x_t,  MROWS * N_EMBED);
    cvt_tf32_kernel<<<592, 256>>>(W_attn, wa_t, N_EMBED * 3 * N_EMBED);
    cvt_tf32_kernel<<<592, 256>>>(W_proj, wp_t, N_EMBED * N_EMBED);

    // 1) QKV GEMM: [8192,1024]tf32 @ [1024,3072]tf32 + b_attn -> fp32
    {
        dim3 grid(3 * N_EMBED / 128, MROWS / 128);
        mma_gemm_kernel<<<grid, 128, G_SMEM_BYTES>>>(x_t, wa_t, b_attn, qkv,
                                                     MROWS, 3 * N_EMBED, N_EMBED);
    }
    // 2) Causal flash attention (y written as tf32 bits)
    {
        dim3 grid(SLEN / 64, NHEADS, BATCH);
        flash_attn_mma_kernel<<<grid, 128, FA_SMEM_BYTES>>>(qkv, yb);
    }
    // 3) Output projection: y(tf32) @ Wproj(tf32) + b_proj -> out fp32
    {
        dim3 grid(N_EMBED / 128, MROWS / 128);
        mma_gemm_kernel<<<grid, 128, G_SMEM_BYTES>>>(yb, wp_t, b_proj, out,
                                                     MROWS, N_EMBED, N_EMBED);
    }
}